// round 14
// baseline (speedup 1.0000x reference)
#include <cuda_runtime.h>

// x1, x2: [N, D] fp32, N=8192, D=1024 row-major.
// ort = dot(colsum(x1), colsum(x2)) / (N*N)
//
// Two kernels (R9 structure — fastest so far), with PDL overlap:
//   K1 triggers programmatic launch completion right after storing partials;
//   K2 launches early (overlapping K1) and gridDependencySynchronize()s
//   before touching the partials.

static constexpr int D    = 1024;
static constexpr int D4   = D / 4;     // 256 float4 per row
static constexpr int NB   = 592;       // K1 grid = 148 SMs * 4 (one wave)
static constexpr int K2B  = 128;       // K2 grid: 128 blocks, 2 float4-cols each

// Scratch (__device__ globals; no allocation allowed)
__device__ float    g_part1[NB * D];   // 2.42 MB
__device__ float    g_part2[NB * D];   // 2.42 MB
__device__ double   g_acc;
__device__ unsigned g_done = 0;

__device__ __forceinline__ void acc4(float4& a, const float4 v) {
    a.x += v.x; a.y += v.y; a.z += v.z; a.w += v.w;
}

// ── K1: per-block partial column sums (at the LTS cap — unchanged body).
__global__ __launch_bounds__(256, 4) void colsum_partials(
    const float4* __restrict__ x1,
    const float4* __restrict__ x2,
    int nrows)
{
    const int t = threadIdx.x;
    const int b = blockIdx.x;

    if (b == 0 && t == 0) { g_acc = 0.0; g_done = 0u; }

    const size_t stride = (size_t)NB * D4;
    size_t off = (size_t)b * D4 + t;

    float4 a10 = make_float4(0.f,0.f,0.f,0.f), a11 = a10;
    float4 a20 = a10, a21 = a10;

    int r = b;
    for (; r + 3 * NB < nrows; r += 4 * NB, off += 4 * stride) {
        const float4 u0 = __ldg(x1 + off);
        const float4 u1 = __ldg(x1 + off +     stride);
        const float4 u2 = __ldg(x1 + off + 2 * stride);
        const float4 u3 = __ldg(x1 + off + 3 * stride);
        const float4 w0 = __ldg(x2 + off);
        const float4 w1 = __ldg(x2 + off +     stride);
        const float4 w2 = __ldg(x2 + off + 2 * stride);
        const float4 w3 = __ldg(x2 + off + 3 * stride);
        acc4(a10, u0); acc4(a11, u1); acc4(a10, u2); acc4(a11, u3);
        acc4(a20, w0); acc4(a21, w1); acc4(a20, w2); acc4(a21, w3);
    }
    for (; r < nrows; r += NB, off += stride) {
        acc4(a10, __ldg(x1 + off));
        acc4(a20, __ldg(x2 + off));
    }

    acc4(a10, a11);
    acc4(a20, a21);
    ((float4*)g_part1)[(size_t)b * D4 + t] = a10;
    ((float4*)g_part2)[(size_t)b * D4 + t] = a20;

#if __CUDA_ARCH__ >= 900
    // Partials stored: let the dependent K2 grid launch now. Memory
    // visibility is provided by K2's cudaGridDependencySynchronize().
    cudaTriggerProgrammaticLaunchCompletion();
#endif
}

// ── K2: finish colsums, dot, finalize (R9 body). Opens with PDL sync.
__global__ __launch_bounds__(256) void reduce_dot_finalize(
    float* __restrict__ out, double inv_count)
{
#if __CUDA_ARCH__ >= 900
    cudaGridDependencySynchronize();   // wait for K1 completion + visibility
#endif

    const int t   = threadIdx.x;
    const int g   = blockIdx.x;
    const int col = t & 1;
    const int rl  = t >> 1;              // 0..127
    const int cv  = g * 2 + col;         // global float4 column

    const float4* __restrict__ p1 = (const float4*)g_part1;
    const float4* __restrict__ p2 = (const float4*)g_part2;

    const size_t st  = (size_t)128 * D4;
    const size_t off = (size_t)rl * D4 + cv;
    const bool tail  = (rl < NB - 512);            // rl < 80 -> 5th row exists
    const size_t off4 = tail ? (off + 4 * st) : off;

    const float4 u0 = p1[off];
    const float4 u1 = p1[off +     st];
    const float4 u2 = p1[off + 2 * st];
    const float4 u3 = p1[off + 3 * st];
    const float4 w0 = p2[off];
    const float4 w1 = p2[off +     st];
    const float4 w2 = p2[off + 2 * st];
    const float4 w3 = p2[off + 3 * st];
    float4 u4 = p1[off4];
    float4 w4 = p2[off4];
    if (!tail) { u4 = make_float4(0.f,0.f,0.f,0.f); w4 = u4; }

    float4 s1 = u0, s2 = w0;
    acc4(s1, u1); acc4(s1, u2); acc4(s1, u3); acc4(s1, u4);
    acc4(s2, w1); acc4(s2, w2); acc4(s2, w3); acc4(s2, w4);

    #pragma unroll
    for (int o = 16; o >= 2; o >>= 1) {
        s1.x += __shfl_down_sync(0xFFFFFFFFu, s1.x, o);
        s1.y += __shfl_down_sync(0xFFFFFFFFu, s1.y, o);
        s1.z += __shfl_down_sync(0xFFFFFFFFu, s1.z, o);
        s1.w += __shfl_down_sync(0xFFFFFFFFu, s1.w, o);
        s2.x += __shfl_down_sync(0xFFFFFFFFu, s2.x, o);
        s2.y += __shfl_down_sync(0xFFFFFFFFu, s2.y, o);
        s2.z += __shfl_down_sync(0xFFFFFFFFu, s2.z, o);
        s2.w += __shfl_down_sync(0xFFFFFFFFu, s2.w, o);
    }

    __shared__ float4 sh1[8][2], sh2[8][2];    // [warp][col]
    const int warp = t >> 5, lane = t & 31;
    if (lane < 2) { sh1[warp][lane] = s1; sh2[warp][lane] = s2; }
    __syncthreads();

    if (warp == 0 && lane < 16) {
        const int w = lane >> 1, c = lane & 1;
        float4 v1 = sh1[w][c], v2 = sh2[w][c];
        #pragma unroll
        for (int o = 8; o >= 2; o >>= 1) {
            v1.x += __shfl_down_sync(0x0000FFFFu, v1.x, o, 16);
            v1.y += __shfl_down_sync(0x0000FFFFu, v1.y, o, 16);
            v1.z += __shfl_down_sync(0x0000FFFFu, v1.z, o, 16);
            v1.w += __shfl_down_sync(0x0000FFFFu, v1.w, o, 16);
            v2.x += __shfl_down_sync(0x0000FFFFu, v2.x, o, 16);
            v2.y += __shfl_down_sync(0x0000FFFFu, v2.y, o, 16);
            v2.z += __shfl_down_sync(0x0000FFFFu, v2.z, o, 16);
            v2.w += __shfl_down_sync(0x0000FFFFu, v2.w, o, 16);
        }
        double d = (double)v1.x * (double)v2.x
                 + (double)v1.y * (double)v2.y
                 + (double)v1.z * (double)v2.z
                 + (double)v1.w * (double)v2.w;
        d += __shfl_down_sync(0x0000FFFFu, d, 1, 16);

        if (lane == 0) {
            atomicAdd(&g_acc, d);
            __threadfence();
            const unsigned dt = atomicAdd(&g_done, 1u);
            if (dt == K2B - 1)
                out[0] = (float)(*(volatile double*)&g_acc * inv_count);
        }
    }
}

extern "C" void kernel_launch(void* const* d_in, const int* in_sizes, int n_in,
                              void* d_out, int out_size)
{
    const float4* x1 = (const float4*)d_in[0];
    const float4* x2 = (const float4*)d_in[1];
    float* out = (float*)d_out;

    const int rows1 = in_sizes[0] / D;   // 8192
    const int rows2 = in_sizes[1] / D;   // 8192
    const double inv_count = 1.0 / ((double)rows1 * (double)rows2);

    colsum_partials<<<NB, 256>>>(x1, x2, rows1);

    // K2 with programmatic dependent launch: overlap its launch with K1.
    cudaLaunchConfig_t cfg = {};
    cfg.gridDim  = dim3(K2B, 1, 1);
    cfg.blockDim = dim3(256, 1, 1);
    cfg.dynamicSmemBytes = 0;
    cfg.stream = 0;
    cudaLaunchAttribute attr[1];
    attr[0].id = cudaLaunchAttributeProgrammaticStreamSerialization;
    attr[0].val.programmaticStreamSerializationAllowed = 1;
    cfg.attrs = attr;
    cfg.numAttrs = 1;
    cudaError_t e = cudaLaunchKernelEx(&cfg, reduce_dot_finalize, out, inv_count);
    if (e != cudaSuccess) {
        // Fallback: plain launch (keeps correctness if PDL capture is rejected)
        reduce_dot_finalize<<<K2B, 256>>>(out, inv_count);
    }
}

// round 17
// speedup vs baseline: 1.5134x; 1.5134x over previous
#include <cuda_runtime.h>

// x1, x2: [N, D] fp32, N=8192, D=1024 row-major.
// ort = dot(colsum(x1), colsum(x2)) / (N*N)

static constexpr int D    = 1024;
static constexpr int D4   = D / 4;     // 256 float4 per row
static constexpr int NB   = 296;       // K1 grid = 148 SMs * 2 (one wave)
static constexpr int K2B  = 64;        // K2 grid: 64 blocks, 4 float4-cols each

// Scratch (__device__ globals; no allocation allowed)
__device__ float    g_part1[NB * D];   // 1.21 MB
__device__ float    g_part2[NB * D];   // 1.21 MB
__device__ double   g_acc;
__device__ unsigned g_done = 0;

__device__ __forceinline__ void acc4(float4& a, const float4 v) {
    a.x += v.x; a.y += v.y; a.z += v.z; a.w += v.w;
}

// ── K1: per-block partial column sums (same proven body, NB=296).
// Each thread owns one float4 column group; 4-row manual unroll gives 8
// batched independent LDG.128; 2 accumulators break the FADD chain.
__global__ __launch_bounds__(256, 2) void colsum_partials(
    const float4* __restrict__ x1,
    const float4* __restrict__ x2,
    int nrows)
{
    const int t = threadIdx.x;
    const int b = blockIdx.x;

    if (b == 0 && t == 0) { g_acc = 0.0; g_done = 0u; }  // K2 ordered after K1

    const size_t stride = (size_t)NB * D4;
    size_t off = (size_t)b * D4 + t;

    float4 a10 = make_float4(0.f,0.f,0.f,0.f), a11 = a10;
    float4 a20 = a10, a21 = a10;

    int r = b;
    for (; r + 3 * NB < nrows; r += 4 * NB, off += 4 * stride) {
        const float4 u0 = __ldg(x1 + off);
        const float4 u1 = __ldg(x1 + off +     stride);
        const float4 u2 = __ldg(x1 + off + 2 * stride);
        const float4 u3 = __ldg(x1 + off + 3 * stride);
        const float4 w0 = __ldg(x2 + off);
        const float4 w1 = __ldg(x2 + off +     stride);
        const float4 w2 = __ldg(x2 + off + 2 * stride);
        const float4 w3 = __ldg(x2 + off + 3 * stride);
        acc4(a10, u0); acc4(a11, u1); acc4(a10, u2); acc4(a11, u3);
        acc4(a20, w0); acc4(a21, w1); acc4(a20, w2); acc4(a21, w3);
    }
    for (; r < nrows; r += NB, off += stride) {
        acc4(a10, __ldg(x1 + off));
        acc4(a20, __ldg(x2 + off));
    }

    acc4(a10, a11);
    acc4(a20, a21);
    ((float4*)g_part1)[(size_t)b * D4 + t] = a10;
    ((float4*)g_part2)[(size_t)b * D4 + t] = a20;
}

// ── K2: finish colsums, dot, finalize. 64 blocks x 256 threads.
// Block g owns float4-cols [4g, 4g+4). Lane layout: col = t&3 (4 lanes read
// 64B contiguous), rl = t>>2 (64 row-lanes). 296 = 4*64 + 40: 4 unconditional
// rows + 1 predicated, ALL 10 loads batched -> one latency exposure.
__global__ __launch_bounds__(256) void reduce_dot_finalize(
    float* __restrict__ out, double inv_count)
{
    const int t   = threadIdx.x;
    const int g   = blockIdx.x;
    const int col = t & 3;
    const int rl  = t >> 2;              // 0..63
    const int cv  = g * 4 + col;         // global float4 column

    const float4* __restrict__ p1 = (const float4*)g_part1;
    const float4* __restrict__ p2 = (const float4*)g_part2;

    const size_t st  = (size_t)64 * D4;            // stride of 64 partial rows
    const size_t off = (size_t)rl * D4 + cv;
    const bool tail  = (rl < NB - 256);            // rl < 40 -> 5th row exists
    const size_t off4 = tail ? (off + 4 * st) : off;  // safe dup if no tail

    const float4 u0 = p1[off];
    const float4 u1 = p1[off +     st];
    const float4 u2 = p1[off + 2 * st];
    const float4 u3 = p1[off + 3 * st];
    const float4 w0 = p2[off];
    const float4 w1 = p2[off +     st];
    const float4 w2 = p2[off + 2 * st];
    const float4 w3 = p2[off + 3 * st];
    float4 u4 = p1[off4];
    float4 w4 = p2[off4];
    if (!tail) { u4 = make_float4(0.f,0.f,0.f,0.f); w4 = u4; }

    float4 s1 = u0, s2 = w0;
    acc4(s1, u1); acc4(s1, u2); acc4(s1, u3); acc4(s1, u4);
    acc4(s2, w1); acc4(s2, w2); acc4(s2, w3); acc4(s2, w4);

    // warp reduce over rl (offsets 16,8,4 preserve col = lane&3)
    #pragma unroll
    for (int o = 16; o >= 4; o >>= 1) {
        s1.x += __shfl_down_sync(0xFFFFFFFFu, s1.x, o);
        s1.y += __shfl_down_sync(0xFFFFFFFFu, s1.y, o);
        s1.z += __shfl_down_sync(0xFFFFFFFFu, s1.z, o);
        s1.w += __shfl_down_sync(0xFFFFFFFFu, s1.w, o);
        s2.x += __shfl_down_sync(0xFFFFFFFFu, s2.x, o);
        s2.y += __shfl_down_sync(0xFFFFFFFFu, s2.y, o);
        s2.z += __shfl_down_sync(0xFFFFFFFFu, s2.z, o);
        s2.w += __shfl_down_sync(0xFFFFFFFFu, s2.w, o);
    }

    __shared__ float4 sh1[8][4], sh2[8][4];    // [warp][col]
    const int warp = t >> 5, lane = t & 31;
    if (lane < 4) { sh1[warp][lane] = s1; sh2[warp][lane] = s2; }
    __syncthreads();

    if (warp == 0) {
        // lane = w*4 + c, w in 0..7: reduce over w with offsets 16,8,4
        const int w = lane >> 2, c = lane & 3;
        float4 v1 = sh1[w][c], v2 = sh2[w][c];
        #pragma unroll
        for (int o = 16; o >= 4; o >>= 1) {
            v1.x += __shfl_down_sync(0xFFFFFFFFu, v1.x, o);
            v1.y += __shfl_down_sync(0xFFFFFFFFu, v1.y, o);
            v1.z += __shfl_down_sync(0xFFFFFFFFu, v1.z, o);
            v1.w += __shfl_down_sync(0xFFFFFFFFu, v1.w, o);
            v2.x += __shfl_down_sync(0xFFFFFFFFu, v2.x, o);
            v2.y += __shfl_down_sync(0xFFFFFFFFu, v2.y, o);
            v2.z += __shfl_down_sync(0xFFFFFFFFu, v2.z, o);
            v2.w += __shfl_down_sync(0xFFFFFFFFu, v2.w, o);
        }
        // lanes 0..3 hold COMPLETE colsums for cols 4g+{0..3} -> dot in double
        double d = (double)v1.x * (double)v2.x
                 + (double)v1.y * (double)v2.y
                 + (double)v1.z * (double)v2.z
                 + (double)v1.w * (double)v2.w;
        // reduce the 4-lane group (width=4)
        d += __shfl_down_sync(0xFFFFFFFFu, d, 2, 4);
        d += __shfl_down_sync(0xFFFFFFFFu, d, 1, 4);

        if (lane == 0) {
            atomicAdd(&g_acc, d);
            __threadfence();
            const unsigned dt = atomicAdd(&g_done, 1u);
            if (dt == K2B - 1)
                out[0] = (float)(*(volatile double*)&g_acc * inv_count);
        }
    }
}

extern "C" void kernel_launch(void* const* d_in, const int* in_sizes, int n_in,
                              void* d_out, int out_size)
{
    const float4* x1 = (const float4*)d_in[0];
    const float4* x2 = (const float4*)d_in[1];
    float* out = (float*)d_out;

    const int rows1 = in_sizes[0] / D;   // 8192
    const int rows2 = in_sizes[1] / D;   // 8192
    const double inv_count = 1.0 / ((double)rows1 * (double)rows2);

    colsum_partials<<<NB, 256>>>(x1, x2, rows1);
    reduce_dot_finalize<<<K2B, 256>>>(out, inv_count);
}